// round 12
// baseline (speedup 1.0000x reference)
#include <cuda_runtime.h>
#include <cuda_bf16.h>
#include <cstdint>
#include <stdint.h>
#include <math.h>

#define T_    4096
#define HID_  4096
#define B_    4
#define S_    1024
#define H_    32
#define HKV_  8
#define D_    128
#define NQKV_ 6144   // (H + 2*HKV) * D

// ---------------- scratch ---------------------------------------------------
__device__ float g_qkv[(size_t)T_ * NQKV_];
__device__ float g_q[(size_t)B_ * H_ * S_ * D_];
__device__ float g_k[(size_t)B_ * HKV_ * S_ * D_];
__device__ float g_v[(size_t)B_ * HKV_ * S_ * D_];
__device__ float g_attn[(size_t)T_ * HID_];
__device__ float g_hid_r[(size_t)T_ * HID_];
__device__ float g_wqkv_r[(size_t)NQKV_ * HID_];
__device__ float g_wd_r[(size_t)HID_ * HID_];

// ---------------- helpers ---------------------------------------------------
__device__ __forceinline__ float to_tf32(float x) {
    unsigned int o;
    asm("cvt.rna.tf32.f32 %0, %1;" : "=r"(o) : "f"(x));
    return __uint_as_float(o);
}

__device__ __forceinline__ void cp16(unsigned int dst, const void* src) {
    asm volatile("cp.async.cg.shared.global [%0], [%1], 16;" :: "r"(dst), "l"(src));
}

__device__ __forceinline__ void mma_tf32(float* c, const unsigned int* a,
                                         const unsigned int* b) {
    asm volatile(
        "mma.sync.aligned.m16n8k8.row.col.f32.tf32.tf32.f32 "
        "{%0,%1,%2,%3}, {%4,%5,%6,%7}, {%8,%9}, {%0,%1,%2,%3};\n"
        : "+f"(c[0]), "+f"(c[1]), "+f"(c[2]), "+f"(c[3])
        : "r"(a[0]), "r"(a[1]), "r"(a[2]), "r"(a[3]), "r"(b[0]), "r"(b[1]));
}

__device__ __forceinline__ void ldsm4(unsigned int* r, unsigned int addr) {
    asm volatile("ldmatrix.sync.aligned.m8n8.x4.shared.b16 {%0,%1,%2,%3}, [%4];"
        : "=r"(r[0]), "=r"(r[1]), "=r"(r[2]), "=r"(r[3]) : "r"(addr));
}

// ---------------- pre-round fp32 -> tf32-canonical fp32 ---------------------
__global__ void round_tf32_kernel(const float* __restrict__ src,
                                  float* __restrict__ dst, int n4)
{
    int i = blockIdx.x * blockDim.x + threadIdx.x;
    if (i < n4) {
        float4 v = ((const float4*)src)[i];
        v.x = to_tf32(v.x); v.y = to_tf32(v.y);
        v.z = to_tf32(v.z); v.w = to_tf32(v.w);
        ((float4*)dst)[i] = v;
    }
}

// ---------------- tf32 tensor-core GEMM: C = A[M,K] * W[N,K]^T --------------
// 128x128x32 tiles, 8 warps (2Mx4N), warp tile 64x32, ldmatrix frags,
// 3-stage cp.async pipeline.
#define BM 128
#define BN 128
#define BK 32
#define LDT 36
#define NSTG 3
#define GEMM_STAGE_BYTES (BM * LDT * 4)                    // 18432 per matrix/stage
#define GEMM_SMEM_BYTES (NSTG * 2 * BM * LDT * 4)          // 110592

__global__ __launch_bounds__(256) void tf32_gemm_nt(
    const float* __restrict__ A, const float* __restrict__ W,
    float* __restrict__ C, int M, int N, int K)
{
    extern __shared__ float sm[];
    float* As = sm;                          // [NSTG][128][36]
    float* Bs = sm + NSTG * BM * LDT;        // [NSTG][128][36]

    const int tid  = threadIdx.x;
    const int warp = tid >> 5, lane = tid & 31;
    const int wm   = (warp >> 2) * 64;
    const int wn   = (warp & 3) * 32;
    const int bm   = blockIdx.y * BM;
    const int bn   = blockIdx.x * BN;

    const unsigned int sA = (unsigned int)__cvta_generic_to_shared(As);
    const unsigned int sB = (unsigned int)__cvta_generic_to_shared(Bs);

    const int l7  = lane & 7;
    const int lg1 = (lane >> 3) & 1;
    const int lg2 = lane >> 4;
    const unsigned int aLane = (unsigned int)(((wm + l7 + 8 * lg1) * LDT + 4 * lg2) * 4);
    const unsigned int bLane = (unsigned int)(((wn + l7 + 8 * lg2) * LDT + 4 * lg1) * 4);

    const int lr = tid >> 3;
    const int lcq = (tid & 7) * 4;

    float acc[4][4][4];
    #pragma unroll
    for (int i = 0; i < 4; i++)
        #pragma unroll
        for (int j = 0; j < 4; j++)
            #pragma unroll
            for (int r = 0; r < 4; r++) acc[i][j][r] = 0.f;

    const int NT = K / BK;

    // prologue: load tiles 0..NSTG-2 into stages 0..NSTG-2
    #pragma unroll
    for (int p = 0; p < NSTG - 1; p++) {
        const int k0 = p * BK;
        #pragma unroll
        for (int i = 0; i < 4; i++) {
            int r = lr + i * 32;
            cp16(sA + (unsigned int)(p * GEMM_STAGE_BYTES + (r * LDT + lcq) * 4),
                 A + (size_t)(bm + r) * K + k0 + lcq);
            cp16(sB + (unsigned int)(p * GEMM_STAGE_BYTES + (r * LDT + lcq) * 4),
                 W + (size_t)(bn + r) * K + k0 + lcq);
        }
        asm volatile("cp.async.commit_group;");
    }

    int cs = 0;            // compute stage
    int ls = NSTG - 1;     // load-target stage (tile kt + NSTG-1)

    for (int kt = 0; kt < NT; kt++) {
        // issue loads for tile kt + NSTG-1 into stage ls (freed last iter)
        if (kt + NSTG - 1 < NT) {
            const int k0 = (kt + NSTG - 1) * BK;
            #pragma unroll
            for (int i = 0; i < 4; i++) {
                int r = lr + i * 32;
                cp16(sA + (unsigned int)(ls * GEMM_STAGE_BYTES + (r * LDT + lcq) * 4),
                     A + (size_t)(bm + r) * K + k0 + lcq);
                cp16(sB + (unsigned int)(ls * GEMM_STAGE_BYTES + (r * LDT + lcq) * 4),
                     W + (size_t)(bn + r) * K + k0 + lcq);
            }
        }
        asm volatile("cp.async.commit_group;");
        // tile kt guaranteed complete with <= NSTG-1 groups pending
        asm volatile("cp.async.wait_group %0;" :: "n"(NSTG - 1));
        __syncthreads();

        const unsigned int aBase = sA + (unsigned int)(cs * GEMM_STAGE_BYTES) + aLane;
        const unsigned int bBase = sB + (unsigned int)(cs * GEMM_STAGE_BYTES) + bLane;

        #pragma unroll
        for (int kk = 0; kk < 4; kk++) {
            unsigned int af[4][4], bf[2][4];
            #pragma unroll
            for (int mt = 0; mt < 4; mt++)
                ldsm4(af[mt], aBase + (unsigned int)(mt * 16 * LDT * 4 + kk * 32));
            #pragma unroll
            for (int j2 = 0; j2 < 2; j2++)
                ldsm4(bf[j2], bBase + (unsigned int)(j2 * 16 * LDT * 4 + kk * 32));
            #pragma unroll
            for (int mt = 0; mt < 4; mt++) {
                #pragma unroll
                for (int j2 = 0; j2 < 2; j2++) {
                    mma_tf32(acc[mt][2 * j2],     af[mt], &bf[j2][0]);
                    mma_tf32(acc[mt][2 * j2 + 1], af[mt], &bf[j2][2]);
                }
            }
        }
        __syncthreads();

        cs = (cs + 1 == NSTG) ? 0 : cs + 1;
        ls = (ls + 1 == NSTG) ? 0 : ls + 1;
    }

    #pragma unroll
    for (int mt = 0; mt < 4; mt++) {
        #pragma unroll
        for (int nt = 0; nt < 4; nt++) {
            const int g  = lane >> 2, t4 = lane & 3;
            const int row0 = bm + wm + mt * 16 + g;
            const int col  = bn + wn + nt * 8 + 2 * t4;
            *(float2*)(C + (size_t)row0 * N + col)       = make_float2(acc[mt][nt][0], acc[mt][nt][1]);
            *(float2*)(C + (size_t)(row0 + 8) * N + col) = make_float2(acc[mt][nt][2], acc[mt][nt][3]);
        }
    }
}

// ---------------- RoPE + scatter (emits tf32-canonical q/k/v) ---------------
__global__ void rope_scatter(const float* __restrict__ qkv,
                             const int* __restrict__ positions,
                             float* __restrict__ Qr, float* __restrict__ Kr,
                             float* __restrict__ Vr)
{
    const int NQ = T_ * H_ * 64;
    const int NK = T_ * HKV_ * 64;
    const int NV = T_ * HKV_ * 128;
    int idx = blockIdx.x * 256 + threadIdx.x;
    const double KF = 0.20762050593046014;  // log2(10000)/64

    if (idx < NQ) {
        int i = idx & 63;
        int h = (idx >> 6) & 31;
        int t = idx >> 11;
        int pos = positions[t];
        const float* row = qkv + (size_t)t * NQKV_ + h * 128;
        float x1 = row[i], x2 = row[64 + i];
        double f = (double)pos * exp2(-(double)i * KF);
        double sv, cv; sincos(f, &sv, &cv);
        float c = (float)cv, s = (float)sv;
        int b = t >> 10, si = t & 1023;
        float* out = Qr + (((size_t)(b * H_ + h)) * S_ + si) * 128;
        out[i]      = to_tf32(x1 * c - x2 * s);
        out[64 + i] = to_tf32(x2 * c + x1 * s);
    } else if (idx < NQ + NK) {
        int r = idx - NQ;
        int i = r & 63;
        int h = (r >> 6) & 7;
        int t = r >> 9;
        int pos = positions[t];
        const float* row = qkv + (size_t)t * NQKV_ + H_ * 128 + h * 128;
        float x1 = row[i], x2 = row[64 + i];
        double f = (double)pos * exp2(-(double)i * KF);
        double sv, cv; sincos(f, &sv, &cv);
        float c = (float)cv, s = (float)sv;
        int b = t >> 10, si = t & 1023;
        float* out = Kr + (((size_t)(b * HKV_ + h)) * S_ + si) * 128;
        out[i]      = to_tf32(x1 * c - x2 * s);
        out[64 + i] = to_tf32(x2 * c + x1 * s);
    } else if (idx < NQ + NK + NV) {
        int r = idx - NQ - NK;
        int i = r & 127;
        int h = (r >> 7) & 7;
        int t = r >> 10;
        int b = t >> 10, si = t & 1023;
        Vr[(((size_t)(b * HKV_ + h)) * S_ + si) * 128 + i] =
            to_tf32(qkv[(size_t)t * NQKV_ + (H_ + HKV_) * 128 + h * 128 + i]);
    }
}

// ---------------- flash attention via tf32 mma + ldmatrix -------------------
#define FA_LDQ 132
#define FA_LDK 132
#define FA_LDV 136
#define FA_LDP 68
#define FA_Q_FLOATS (128 * FA_LDQ)
#define FA_K_FLOATS (64 * FA_LDK)
#define FA_V_FLOATS (64 * FA_LDV)
#define FA_P_FLOATS (128 * FA_LDP)
#define FA_SMEM_BYTES ((FA_Q_FLOATS + FA_K_FLOATS + FA_V_FLOATS + FA_P_FLOATS) * 4)

__global__ __launch_bounds__(256) void flash_attn_mma(
    const float* __restrict__ Q, const float* __restrict__ Kg,
    const float* __restrict__ Vg, float* __restrict__ Out)
{
    extern __shared__ float sm[];
    float* Qs = sm;
    float* Ks = Qs + FA_Q_FLOATS;
    float* Vs = Ks + FA_K_FLOATS;
    float* Ps = Vs + FA_V_FLOATS;

    const int qb = blockIdx.x;
    const int bh = blockIdx.y;
    const int b  = bh >> 5;
    const int h  = bh & 31;
    const int hkv = h >> 2;

    const float* Qbase = Q  + ((size_t)bh * S_ + qb * 128) * D_;
    const float* Kbase = Kg + ((size_t)(b * HKV_ + hkv) * S_) * D_;
    const float* Vbase = Vg + ((size_t)(b * HKV_ + hkv) * S_) * D_;

    const int tid  = threadIdx.x;
    const int w    = tid >> 5, lane = tid & 31;
    const int g    = lane >> 2, t4 = lane & 3;
    const int wrow = w * 16;
    const float C = 0.12751743199276533f;   // (1/sqrt(128)) * log2(e)

    const unsigned int sQ = (unsigned int)__cvta_generic_to_shared(Qs);
    const unsigned int sK = (unsigned int)__cvta_generic_to_shared(Ks);
    const unsigned int sV = (unsigned int)__cvta_generic_to_shared(Vs);
    const unsigned int sP = (unsigned int)__cvta_generic_to_shared(Ps);

    const int l7  = lane & 7;
    const int lg1 = (lane >> 3) & 1;
    const int lg2 = lane >> 4;
    const unsigned int qLane = (unsigned int)(((wrow + l7 + 8 * lg1) * FA_LDQ + 4 * lg2) * 4);
    const unsigned int kLane = (unsigned int)(((l7 + 8 * lg2) * FA_LDK + 4 * lg1) * 4);
    const unsigned int pLane = (unsigned int)(((wrow + l7 + 8 * lg1) * FA_LDP + 4 * lg2) * 4);

    for (int i = tid; i < 128 * 32; i += 256) {
        int r = i >> 5, c = (i & 31) << 2;
        *(float4*)&Qs[r * FA_LDQ + c] = *(const float4*)(Qbase + r * 128 + c);
    }

    float O[16][4];
    #pragma unroll
    for (int n = 0; n < 16; n++)
        #pragma unroll
        for (int r = 0; r < 4; r++) O[n][r] = 0.f;
    float m0 = -1e30f, m1 = -1e30f, l0 = 0.f, l1 = 0.f;

    const int jmax = 2 * qb + 1;
    for (int j = 0; j <= jmax; j++) {
        __syncthreads();
        for (int i = tid; i < 64 * 32; i += 256) {
            int r = i >> 5, c = (i & 31) << 2;
            cp16(sK + (unsigned int)((r * FA_LDK + c) * 4), Kbase + (j * 64 + r) * 128 + c);
            cp16(sV + (unsigned int)((r * FA_LDV + c) * 4), Vbase + (j * 64 + r) * 128 + c);
        }
        asm volatile("cp.async.commit_group;");
        asm volatile("cp.async.wait_group 0;");
        __syncthreads();

        if (j * 64 > qb * 128 + wrow + 15) continue;

        float sfr[8][4];
        #pragma unroll
        for (int n = 0; n < 8; n++)
            #pragma unroll
            for (int r = 0; r < 4; r++) sfr[n][r] = 0.f;

        #pragma unroll
        for (int kc = 0; kc < 16; kc++) {
            unsigned int a[4];
            ldsm4(a, sQ + qLane + (unsigned int)(kc * 32));
            #pragma unroll
            for (int j2 = 0; j2 < 4; j2++) {
                unsigned int bfr[4];
                ldsm4(bfr, sK + kLane + (unsigned int)(j2 * 16 * FA_LDK * 4 + kc * 32));
                mma_tf32(sfr[2 * j2],     a, &bfr[0]);
                mma_tf32(sfr[2 * j2 + 1], a, &bfr[2]);
            }
        }

        const int qpos0 = qb * 128 + wrow + g;
        const int qpos1 = qpos0 + 8;
        if (j * 64 + 63 > qb * 128 + wrow) {
            #pragma unroll
            for (int nt = 0; nt < 8; nt++) {
                const int kc0 = j * 64 + nt * 8 + 2 * t4;
                if (kc0     > qpos0) sfr[nt][0] = -1e30f;
                if (kc0 + 1 > qpos0) sfr[nt][1] = -1e30f;
                if (kc0     > qpos1) sfr[nt][2] = -1e30f;
                if (kc0 + 1 > qpos1) sfr[nt][3] = -1e30f;
            }
        }

        float rm0 = -1e30f, rm1 = -1e30f;
        #pragma unroll
        for (int nt = 0; nt < 8; nt++) {
            rm0 = fmaxf(rm0, fmaxf(sfr[nt][0], sfr[nt][1]));
            rm1 = fmaxf(rm1, fmaxf(sfr[nt][2], sfr[nt][3]));
        }
        rm0 = fmaxf(rm0, __shfl_xor_sync(0xffffffffu, rm0, 1));
        rm0 = fmaxf(rm0, __shfl_xor_sync(0xffffffffu, rm0, 2));
        rm1 = fmaxf(rm1, __shfl_xor_sync(0xffffffffu, rm1, 1));
        rm1 = fmaxf(rm1, __shfl_xor_sync(0xffffffffu, rm1, 2));

        const float mn0 = fmaxf(m0, rm0);
        const float mn1 = fmaxf(m1, rm1);
        const float corr0 = exp2f((m0 - mn0) * C);
        const float corr1 = exp2f((m1 - mn1) * C);
        #pragma unroll
        for (int nt = 0; nt < 16; nt++) {
            O[nt][0] *= corr0; O[nt][1] *= corr0;
            O[nt][2] *= corr1; O[nt][3] *= corr1;
        }

        float ls0 = 0.f, ls1 = 0.f;
        #pragma unroll
        for (int nt = 0; nt < 8; nt++) {
            float p00 = to_tf32(exp2f((sfr[nt][0] - mn0) * C));
            float p01 = to_tf32(exp2f((sfr[nt][1] - mn0) * C));
            float p10 = to_tf32(exp2f((sfr[nt][2] - mn1) * C));
            float p11 = to_tf32(exp2f((sfr[nt][3] - mn1) * C));
            ls0 += p00 + p01;
            ls1 += p10 + p11;
            const int col = nt * 8 + 2 * t4;
            *(float2*)&Ps[(wrow + g)     * FA_LDP + col] = make_float2(p00, p01);
            *(float2*)&Ps[(wrow + g + 8) * FA_LDP + col] = make_float2(p10, p11);
        }
        ls0 += __shfl_xor_sync(0xffffffffu, ls0, 1);
        ls0 += __shfl_xor_sync(0xffffffffu, ls0, 2);
        ls1 += __shfl_xor_sync(0xffffffffu, ls1, 1);
        ls1 += __shfl_xor_sync(0xffffffffu, ls1, 2);
        l0 = l0 * corr0 + ls0;
        l1 = l1 * corr1 + ls1;
        m0 = mn0; m1 = mn1;

        __syncwarp();

        #pragma unroll
        for (int kc = 0; kc < 8; kc++) {
            const int k8 = kc * 8;
            unsigned int a[4];
            ldsm4(a, sP + pLane + (unsigned int)(kc * 32));
            #pragma unroll
            for (int nt = 0; nt < 16; nt++) {
                unsigned int bfr[2];
                bfr[0] = __float_as_uint(Vs[(k8 + t4)     * FA_LDV + nt * 8 + g]);
                bfr[1] = __float_as_uint(Vs[(k8 + t4 + 4) * FA_LDV + nt * 8 + g]);
                mma_tf32(O[nt], a, bfr);
            }
        }
    }

    const float il0 = 1.f / l0;
    const float il1 = 1.f / l1;
    const int trow = b * S_ + qb * 128 + wrow + g;
    float* o0 = Out + (size_t)trow * HID_ + h * 128;
    float* o1 = o0 + (size_t)8 * HID_;
    #pragma unroll
    for (int nt = 0; nt < 16; nt++) {
        const int col = nt * 8 + 2 * t4;
        *(float2*)(o0 + col) = make_float2(to_tf32(O[nt][0] * il0), to_tf32(O[nt][1] * il0));
        *(float2*)(o1 + col) = make_float2(to_tf32(O[nt][2] * il1), to_tf32(O[nt][3] * il1));
    }
}

// ---------------- launch -----------------------------------------------------
extern "C" void kernel_launch(void* const* d_in, const int* in_sizes, int n_in,
                              void* d_out, int out_size)
{
    const int*   positions = (const int*)d_in[0];
    const float* hidden    = (const float*)d_in[1];
    const float* w_qkv     = (const float*)d_in[2];
    const float* w_dense   = (const float*)d_in[3];
    float*       out       = (float*)d_out;

    float *qkv, *q, *k, *v, *attn, *hid_r, *wqkv_r, *wd_r;
    cudaGetSymbolAddress((void**)&qkv,    g_qkv);
    cudaGetSymbolAddress((void**)&q,      g_q);
    cudaGetSymbolAddress((void**)&k,      g_k);
    cudaGetSymbolAddress((void**)&v,      g_v);
    cudaGetSymbolAddress((void**)&attn,   g_attn);
    cudaGetSymbolAddress((void**)&hid_r,  g_hid_r);
    cudaGetSymbolAddress((void**)&wqkv_r, g_wqkv_r);
    cudaGetSymbolAddress((void**)&wd_r,   g_wd_r);

    // 0) pre-round GEMM operands to canonical tf32
    {
        int n4;
        n4 = (T_ * HID_) / 4;
        round_tf32_kernel<<<(n4 + 255) / 256, 256>>>(hidden, hid_r, n4);
        n4 = (NQKV_ * HID_) / 4;
        round_tf32_kernel<<<(n4 + 255) / 256, 256>>>(w_qkv, wqkv_r, n4);
        n4 = (HID_ * HID_) / 4;
        round_tf32_kernel<<<(n4 + 255) / 256, 256>>>(w_dense, wd_r, n4);
    }

    // 1) QKV projection
    cudaFuncSetAttribute(tf32_gemm_nt, cudaFuncAttributeMaxDynamicSharedMemorySize,
                         GEMM_SMEM_BYTES);
    tf32_gemm_nt<<<dim3(NQKV_ / BN, T_ / BM), 256, GEMM_SMEM_BYTES>>>(
        hid_r, wqkv_r, qkv, T_, NQKV_, HID_);

    // 2) RoPE + scatter (tf32-canonical outputs)
    const int n_rope = T_ * H_ * 64 + T_ * HKV_ * 64 + T_ * HKV_ * 128;
    rope_scatter<<<(n_rope + 255) / 256, 256>>>(qkv, positions, q, k, v);

    // 3) flash attention
    cudaFuncSetAttribute(flash_attn_mma, cudaFuncAttributeMaxDynamicSharedMemorySize,
                         FA_SMEM_BYTES);
    flash_attn_mma<<<dim3(S_ / 128, B_ * H_), 256, FA_SMEM_BYTES>>>(q, k, v, attn);

    // 4) dense projection
    tf32_gemm_nt<<<dim3(HID_ / 128, T_ / BM), 256, GEMM_SMEM_BYTES>>>(
        attn, wd_r, out, T_, HID_, HID_);
}

// round 13
// speedup vs baseline: 1.6155x; 1.6155x over previous
#include <cuda_runtime.h>
#include <cuda_fp16.h>
#include <cstdint>
#include <stdint.h>
#include <math.h>

#define T_    4096
#define HID_  4096
#define B_    4
#define S_    1024
#define H_    32
#define HKV_  8
#define D_    128
#define NQKV_ 6144   // (H + 2*HKV) * D

// ---------------- scratch ---------------------------------------------------
__device__ float  g_qkv[(size_t)T_ * NQKV_];            // fp32 GEMM output
__device__ __half g_q[(size_t)B_ * H_ * S_ * D_];
__device__ __half g_k[(size_t)B_ * HKV_ * S_ * D_];
__device__ __half g_v[(size_t)B_ * HKV_ * S_ * D_];
__device__ __half g_attn[(size_t)T_ * HID_];
__device__ __half g_hid_h[(size_t)T_ * HID_];
__device__ __half g_wqkv_h[(size_t)NQKV_ * HID_];
__device__ __half g_wd_h[(size_t)HID_ * HID_];

// ---------------- helpers ---------------------------------------------------
__device__ __forceinline__ void cp16(unsigned int dst, const void* src) {
    asm volatile("cp.async.cg.shared.global [%0], [%1], 16;" :: "r"(dst), "l"(src));
}

__device__ __forceinline__ void mma_f16(float* c, const unsigned int* a,
                                        const unsigned int* b) {
    asm volatile(
        "mma.sync.aligned.m16n8k16.row.col.f32.f16.f16.f32 "
        "{%0,%1,%2,%3}, {%4,%5,%6,%7}, {%8,%9}, {%0,%1,%2,%3};\n"
        : "+f"(c[0]), "+f"(c[1]), "+f"(c[2]), "+f"(c[3])
        : "r"(a[0]), "r"(a[1]), "r"(a[2]), "r"(a[3]), "r"(b[0]), "r"(b[1]));
}

__device__ __forceinline__ void ldsm4(unsigned int* r, unsigned int addr) {
    asm volatile("ldmatrix.sync.aligned.m8n8.x4.shared.b16 {%0,%1,%2,%3}, [%4];"
        : "=r"(r[0]), "=r"(r[1]), "=r"(r[2]), "=r"(r[3]) : "r"(addr));
}

__device__ __forceinline__ void ldsm4t(unsigned int* r, unsigned int addr) {
    asm volatile("ldmatrix.sync.aligned.m8n8.x4.trans.shared.b16 {%0,%1,%2,%3}, [%4];"
        : "=r"(r[0]), "=r"(r[1]), "=r"(r[2]), "=r"(r[3]) : "r"(addr));
}

// ---------------- convert fp32 -> fp16 (RN) ---------------------------------
__global__ void to_half_kernel(const float* __restrict__ src,
                               __half* __restrict__ dst, int n4)
{
    int i = blockIdx.x * blockDim.x + threadIdx.x;
    if (i < n4) {
        float4 v = ((const float4*)src)[i];
        __half2 h0 = __floats2half2_rn(v.x, v.y);
        __half2 h1 = __floats2half2_rn(v.z, v.w);
        ((__half2*)dst)[2 * i]     = h0;
        ((__half2*)dst)[2 * i + 1] = h1;
    }
}

// ---------------- fp16 tensor-core GEMM: C = A[M,K] * W[N,K]^T --------------
// A, W fp16; C fp32. 128x128 tiles, BK=64 halves, 8 warps (2Mx4N),
// warp tile 64x32, m16n8k16, ldmatrix frags, 2-stage cp.async.
#define BM 128
#define BN 128
#define LDT 36    // word (4B) pitch: 32 data words (64 halves) + 4 pad
#define GEMM_STAGE_BYTES (BM * LDT * 4)              // 18432 per matrix/stage
#define GEMM_SMEM_BYTES (2 * 2 * BM * LDT * 4)       // 73728

__global__ __launch_bounds__(256) void h16_gemm_nt(
    const __half* __restrict__ A, const __half* __restrict__ W,
    float* __restrict__ C, int M, int N, int K)
{
    extern __shared__ float sm[];
    float* As = sm;
    float* Bs = sm + 2 * BM * LDT;

    const int tid  = threadIdx.x;
    const int warp = tid >> 5, lane = tid & 31;
    const int wm   = (warp >> 2) * 64;
    const int wn   = (warp & 3) * 32;
    const int bm   = blockIdx.y * BM;
    const int bn   = blockIdx.x * BN;

    const unsigned int sA = (unsigned int)__cvta_generic_to_shared(As);
    const unsigned int sB = (unsigned int)__cvta_generic_to_shared(Bs);

    const int l7  = lane & 7;
    const int lg1 = (lane >> 3) & 1;
    const int lg2 = lane >> 4;
    const unsigned int aLane = (unsigned int)(((wm + l7 + 8 * lg1) * LDT + 4 * lg2) * 4);
    const unsigned int bLane = (unsigned int)(((wn + l7 + 8 * lg2) * LDT + 4 * lg1) * 4);

    const int lr  = tid >> 3;            // rows lr, +32, +64, +96
    const int lch = (tid & 7) * 8;       // half-offset within 64-half row chunk
    const int lcw = (tid & 7) * 4;       // word col in smem

    float acc[4][4][4];
    #pragma unroll
    for (int i = 0; i < 4; i++)
        #pragma unroll
        for (int j = 0; j < 4; j++)
            #pragma unroll
            for (int r = 0; r < 4; r++) acc[i][j][r] = 0.f;

    const int NT = K >> 6;   // BK = 64 halves

    #pragma unroll
    for (int i = 0; i < 4; i++) {
        int r = lr + i * 32;
        cp16(sA + (unsigned int)((r * LDT + lcw) * 4), A + (size_t)(bm + r) * K + lch);
        cp16(sB + (unsigned int)((r * LDT + lcw) * 4), W + (size_t)(bn + r) * K + lch);
    }
    asm volatile("cp.async.commit_group;");

    for (int kt = 0; kt < NT; kt++) {
        const int buf = kt & 1;
        if (kt + 1 < NT) {
            const int nb = buf ^ 1;
            const int k0 = (kt + 1) * 64;
            #pragma unroll
            for (int i = 0; i < 4; i++) {
                int r = lr + i * 32;
                cp16(sA + (unsigned int)(((nb * BM + r) * LDT + lcw) * 4),
                     A + (size_t)(bm + r) * K + k0 + lch);
                cp16(sB + (unsigned int)(((nb * BM + r) * LDT + lcw) * 4),
                     W + (size_t)(bn + r) * K + k0 + lch);
            }
            asm volatile("cp.async.commit_group;");
            asm volatile("cp.async.wait_group 1;");
        } else {
            asm volatile("cp.async.wait_group 0;");
        }
        __syncthreads();

        const unsigned int aBase = sA + (unsigned int)(buf * GEMM_STAGE_BYTES) + aLane;
        const unsigned int bBase = sB + (unsigned int)(buf * GEMM_STAGE_BYTES) + bLane;

        // 4 k-steps of k16 (8 words each)
        #pragma unroll
        for (int kk = 0; kk < 4; kk++) {
            unsigned int af[4][4], bf[2][4];
            #pragma unroll
            for (int mt = 0; mt < 4; mt++)
                ldsm4(af[mt], aBase + (unsigned int)(mt * 16 * LDT * 4 + kk * 32));
            #pragma unroll
            for (int j2 = 0; j2 < 2; j2++)
                ldsm4(bf[j2], bBase + (unsigned int)(j2 * 16 * LDT * 4 + kk * 32));
            #pragma unroll
            for (int mt = 0; mt < 4; mt++) {
                #pragma unroll
                for (int j2 = 0; j2 < 2; j2++) {
                    mma_f16(acc[mt][2 * j2],     af[mt], &bf[j2][0]);
                    mma_f16(acc[mt][2 * j2 + 1], af[mt], &bf[j2][2]);
                }
            }
        }
        __syncthreads();
    }

    #pragma unroll
    for (int mt = 0; mt < 4; mt++) {
        #pragma unroll
        for (int nt = 0; nt < 4; nt++) {
            const int g  = lane >> 2, t4 = lane & 3;
            const int row0 = bm + wm + mt * 16 + g;
            const int col  = bn + wn + nt * 8 + 2 * t4;
            *(float2*)(C + (size_t)row0 * N + col)       = make_float2(acc[mt][nt][0], acc[mt][nt][1]);
            *(float2*)(C + (size_t)(row0 + 8) * N + col) = make_float2(acc[mt][nt][2], acc[mt][nt][3]);
        }
    }
}

// ---------------- RoPE + scatter (emits fp16 q/k/v) -------------------------
__global__ void rope_scatter(const float* __restrict__ qkv,
                             const int* __restrict__ positions,
                             __half* __restrict__ Qr, __half* __restrict__ Kr,
                             __half* __restrict__ Vr)
{
    const int NQ = T_ * H_ * 64;
    const int NK = T_ * HKV_ * 64;
    const int NV = T_ * HKV_ * 128;
    int idx = blockIdx.x * 256 + threadIdx.x;
    const double KF = 0.20762050593046014;  // log2(10000)/64

    if (idx < NQ) {
        int i = idx & 63;
        int h = (idx >> 6) & 31;
        int t = idx >> 11;
        int pos = positions[t];
        const float* row = qkv + (size_t)t * NQKV_ + h * 128;
        float x1 = row[i], x2 = row[64 + i];
        double f = (double)pos * exp2(-(double)i * KF);
        double sv, cv; sincos(f, &sv, &cv);
        float c = (float)cv, s = (float)sv;
        int b = t >> 10, si = t & 1023;
        __half* out = Qr + (((size_t)(b * H_ + h)) * S_ + si) * 128;
        out[i]      = __float2half_rn(x1 * c - x2 * s);
        out[64 + i] = __float2half_rn(x2 * c + x1 * s);
    } else if (idx < NQ + NK) {
        int r = idx - NQ;
        int i = r & 63;
        int h = (r >> 6) & 7;
        int t = r >> 9;
        int pos = positions[t];
        const float* row = qkv + (size_t)t * NQKV_ + H_ * 128 + h * 128;
        float x1 = row[i], x2 = row[64 + i];
        double f = (double)pos * exp2(-(double)i * KF);
        double sv, cv; sincos(f, &sv, &cv);
        float c = (float)cv, s = (float)sv;
        int b = t >> 10, si = t & 1023;
        __half* out = Kr + (((size_t)(b * HKV_ + h)) * S_ + si) * 128;
        out[i]      = __float2half_rn(x1 * c - x2 * s);
        out[64 + i] = __float2half_rn(x2 * c + x1 * s);
    } else if (idx < NQ + NK + NV) {
        int r = idx - NQ - NK;
        int i = r & 127;
        int h = (r >> 7) & 7;
        int t = r >> 10;
        int b = t >> 10, si = t & 1023;
        Vr[(((size_t)(b * HKV_ + h)) * S_ + si) * 128 + i] =
            __float2half_rn(qkv[(size_t)t * NQKV_ + (H_ + HKV_) * 128 + h * 128 + i]);
    }
}

// ---------------- flash attention, fp16 mma ---------------------------------
// grid (S/128, B*H), 256 thr (8 warps x m16). K tiles of 64.
// smem word-pitches: Q/K/V rows 68 words (64 data + 4 pad), P rows 36 words.
#define FA_LQ 68
#define FA_LP 36
#define FA_Q_WORDS (128 * FA_LQ)
#define FA_K_WORDS (64 * FA_LQ)
#define FA_V_WORDS (64 * FA_LQ)
#define FA_P_WORDS (128 * FA_LP)
#define FA_SMEM_BYTES ((FA_Q_WORDS + FA_K_WORDS + FA_V_WORDS + FA_P_WORDS) * 4)  // 88064

__global__ __launch_bounds__(256, 2) void flash_attn_h16(
    const __half* __restrict__ Q, const __half* __restrict__ Kg,
    const __half* __restrict__ Vg, __half* __restrict__ Out)
{
    extern __shared__ float sm[];
    float* Qs = sm;
    float* Ks = Qs + FA_Q_WORDS;
    float* Vs = Ks + FA_K_WORDS;
    float* Ps = Vs + FA_V_WORDS;

    const int qb = blockIdx.x;
    const int bh = blockIdx.y;
    const int b  = bh >> 5;
    const int h  = bh & 31;
    const int hkv = h >> 2;

    const __half* Qbase = Q  + ((size_t)bh * S_ + qb * 128) * D_;
    const __half* Kbase = Kg + ((size_t)(b * HKV_ + hkv) * S_) * D_;
    const __half* Vbase = Vg + ((size_t)(b * HKV_ + hkv) * S_) * D_;

    const int tid  = threadIdx.x;
    const int w    = tid >> 5, lane = tid & 31;
    const int g    = lane >> 2, t4 = lane & 3;
    const int wrow = w * 16;
    const float C = 0.12751743199276533f;   // (1/sqrt(128)) * log2(e)

    const unsigned int sQ = (unsigned int)__cvta_generic_to_shared(Qs);
    const unsigned int sK = (unsigned int)__cvta_generic_to_shared(Ks);
    const unsigned int sV = (unsigned int)__cvta_generic_to_shared(Vs);
    const unsigned int sP = (unsigned int)__cvta_generic_to_shared(Ps);

    const int l7  = lane & 7;
    const int lg1 = (lane >> 3) & 1;
    const int lg2 = lane >> 4;
    const unsigned int qLane = (unsigned int)(((wrow + l7 + 8 * lg1) * FA_LQ + 4 * lg2) * 4);
    const unsigned int kLane = (unsigned int)(((l7 + 8 * lg2) * FA_LQ + 4 * lg1) * 4);
    const unsigned int pLane = (unsigned int)(((wrow + l7 + 8 * lg1) * FA_LP + 4 * lg2) * 4);
    // V trans-ldsm: rows = kpos (l7 + 8*lg1), col halves +8 per lg2 (16B)
    const unsigned int vLane = (unsigned int)((l7 + 8 * lg1) * FA_LQ * 4 + lg2 * 16);

    // load Q tile: 128 rows x 128 halves (16 chunks of 16B per row)
    for (int i = tid; i < 128 * 16; i += 256) {
        int r = i >> 4, c = i & 15;
        cp16(sQ + (unsigned int)((r * FA_LQ + c * 4) * 4), Qbase + r * 128 + c * 8);
    }
    asm volatile("cp.async.commit_group;");

    float O[16][4];
    #pragma unroll
    for (int n = 0; n < 16; n++)
        #pragma unroll
        for (int r = 0; r < 4; r++) O[n][r] = 0.f;
    float m0 = -1e30f, m1 = -1e30f, l0 = 0.f, l1 = 0.f;

    const int jmax = 2 * qb + 1;
    for (int j = 0; j <= jmax; j++) {
        __syncthreads();
        for (int i = tid; i < 64 * 16; i += 256) {
            int r = i >> 4, c = i & 15;
            cp16(sK + (unsigned int)((r * FA_LQ + c * 4) * 4), Kbase + (j * 64 + r) * 128 + c * 8);
            cp16(sV + (unsigned int)((r * FA_LQ + c * 4) * 4), Vbase + (j * 64 + r) * 128 + c * 8);
        }
        asm volatile("cp.async.commit_group;");
        asm volatile("cp.async.wait_group 0;");
        __syncthreads();

        if (j * 64 > qb * 128 + wrow + 15) continue;

        // ---- S = Q Kt : 8 k-steps of k16 ----
        float sfr[8][4];
        #pragma unroll
        for (int n = 0; n < 8; n++)
            #pragma unroll
            for (int r = 0; r < 4; r++) sfr[n][r] = 0.f;

        #pragma unroll
        for (int kk = 0; kk < 8; kk++) {
            unsigned int a[4];
            ldsm4(a, sQ + qLane + (unsigned int)(kk * 32));
            #pragma unroll
            for (int j2 = 0; j2 < 4; j2++) {
                unsigned int bfr[4];
                ldsm4(bfr, sK + kLane + (unsigned int)(j2 * 16 * FA_LQ * 4 + kk * 32));
                mma_f16(sfr[2 * j2],     a, &bfr[0]);
                mma_f16(sfr[2 * j2 + 1], a, &bfr[2]);
            }
        }

        // ---- causal mask ----
        const int qpos0 = qb * 128 + wrow + g;
        const int qpos1 = qpos0 + 8;
        if (j * 64 + 63 > qb * 128 + wrow) {
            #pragma unroll
            for (int nt = 0; nt < 8; nt++) {
                const int kc0 = j * 64 + nt * 8 + 2 * t4;
                if (kc0     > qpos0) sfr[nt][0] = -1e30f;
                if (kc0 + 1 > qpos0) sfr[nt][1] = -1e30f;
                if (kc0     > qpos1) sfr[nt][2] = -1e30f;
                if (kc0 + 1 > qpos1) sfr[nt][3] = -1e30f;
            }
        }

        // ---- online softmax ----
        float rm0 = -1e30f, rm1 = -1e30f;
        #pragma unroll
        for (int nt = 0; nt < 8; nt++) {
            rm0 = fmaxf(rm0, fmaxf(sfr[nt][0], sfr[nt][1]));
            rm1 = fmaxf(rm1, fmaxf(sfr[nt][2], sfr[nt][3]));
        }
        rm0 = fmaxf(rm0, __shfl_xor_sync(0xffffffffu, rm0, 1));
        rm0 = fmaxf(rm0, __shfl_xor_sync(0xffffffffu, rm0, 2));
        rm1 = fmaxf(rm1, __shfl_xor_sync(0xffffffffu, rm1, 1));
        rm1 = fmaxf(rm1, __shfl_xor_sync(0xffffffffu, rm1, 2));

        const float mn0 = fmaxf(m0, rm0);
        const float mn1 = fmaxf(m1, rm1);
        const float corr0 = exp2f((m0 - mn0) * C);
        const float corr1 = exp2f((m1 - mn1) * C);
        #pragma unroll
        for (int nt = 0; nt < 16; nt++) {
            O[nt][0] *= corr0; O[nt][1] *= corr0;
            O[nt][2] *= corr1; O[nt][3] *= corr1;
        }

        float ls0 = 0.f, ls1 = 0.f;
        #pragma unroll
        for (int nt = 0; nt < 8; nt++) {
            __half2 h0 = __floats2half2_rn(exp2f((sfr[nt][0] - mn0) * C),
                                           exp2f((sfr[nt][1] - mn0) * C));
            __half2 h1 = __floats2half2_rn(exp2f((sfr[nt][2] - mn1) * C),
                                           exp2f((sfr[nt][3] - mn1) * C));
            float2 f0 = __half22float2(h0);
            float2 f1 = __half22float2(h1);
            ls0 += f0.x + f0.y;
            ls1 += f1.x + f1.y;
            // P word col = kpos/2 = nt*4 + t4
            ((__half2*)Ps)[(wrow + g)     * FA_LP + nt * 4 + t4] = h0;
            ((__half2*)Ps)[(wrow + g + 8) * FA_LP + nt * 4 + t4] = h1;
        }
        ls0 += __shfl_xor_sync(0xffffffffu, ls0, 1);
        ls0 += __shfl_xor_sync(0xffffffffu, ls0, 2);
        ls1 += __shfl_xor_sync(0xffffffffu, ls1, 1);
        ls1 += __shfl_xor_sync(0xffffffffu, ls1, 2);
        l0 = l0 * corr0 + ls0;
        l1 = l1 * corr1 + ls1;
        m0 = mn0; m1 = mn1;

        __syncwarp();   // P rows are warp-private

        // ---- O += P V : 4 k-steps of k16 over kpos ----
        #pragma unroll
        for (int kk = 0; kk < 4; kk++) {
            unsigned int a[4];
            ldsm4(a, sP + pLane + (unsigned int)(kk * 32));
            #pragma unroll
            for (int jp = 0; jp < 8; jp++) {
                unsigned int bfr[4];
                ldsm4t(bfr, sV + vLane + (unsigned int)(kk * 16 * FA_LQ * 4 + jp * 32));
                mma_f16(O[2 * jp],     a, &bfr[0]);
                mma_f16(O[2 * jp + 1], a, &bfr[2]);
            }
        }
    }

    // ---- epilogue: normalize, fp16 store to attn [T, H*D] ----
    const float il0 = 1.f / l0;
    const float il1 = 1.f / l1;
    const int trow = b * S_ + qb * 128 + wrow + g;
    __half* o0 = Out + (size_t)trow * HID_ + h * 128;
    __half* o1 = o0 + (size_t)8 * HID_;
    #pragma unroll
    for (int nt = 0; nt < 16; nt++) {
        const int col = nt * 8 + 2 * t4;
        *(__half2*)(o0 + col) = __floats2half2_rn(O[nt][0] * il0, O[nt][1] * il0);
        *(__half2*)(o1 + col) = __floats2half2_rn(O[nt][2] * il1, O[nt][3] * il1);
    }
}

// ---------------- launch -----------------------------------------------------
extern "C" void kernel_launch(void* const* d_in, const int* in_sizes, int n_in,
                              void* d_out, int out_size)
{
    const int*   positions = (const int*)d_in[0];
    const float* hidden    = (const float*)d_in[1];
    const float* w_qkv     = (const float*)d_in[2];
    const float* w_dense   = (const float*)d_in[3];
    float*       out       = (float*)d_out;

    float *qkv;
    __half *q, *k, *v, *attn, *hid_h, *wqkv_h, *wd_h;
    cudaGetSymbolAddress((void**)&qkv,    g_qkv);
    cudaGetSymbolAddress((void**)&q,      g_q);
    cudaGetSymbolAddress((void**)&k,      g_k);
    cudaGetSymbolAddress((void**)&v,      g_v);
    cudaGetSymbolAddress((void**)&attn,   g_attn);
    cudaGetSymbolAddress((void**)&hid_h,  g_hid_h);
    cudaGetSymbolAddress((void**)&wqkv_h, g_wqkv_h);
    cudaGetSymbolAddress((void**)&wd_h,   g_wd_h);

    // 0) convert GEMM operands to fp16
    {
        int n4;
        n4 = (T_ * HID_) / 4;
        to_half_kernel<<<(n4 + 255) / 256, 256>>>(hidden, hid_h, n4);
        n4 = (NQKV_ * HID_) / 4;
        to_half_kernel<<<(n4 + 255) / 256, 256>>>(w_qkv, wqkv_h, n4);
        n4 = (HID_ * HID_) / 4;
        to_half_kernel<<<(n4 + 255) / 256, 256>>>(w_dense, wd_h, n4);
    }

    // 1) QKV projection (fp16 mma, fp32 accum/output)
    cudaFuncSetAttribute(h16_gemm_nt, cudaFuncAttributeMaxDynamicSharedMemorySize,
                         GEMM_SMEM_BYTES);
    h16_gemm_nt<<<dim3(NQKV_ / BN, T_ / BM), 256, GEMM_SMEM_BYTES>>>(
        hid_h, wqkv_h, qkv, T_, NQKV_, HID_);

    // 2) RoPE + scatter (fp16 q/k/v)
    const int n_rope = T_ * H_ * 64 + T_ * HKV_ * 64 + T_ * HKV_ * 128;
    rope_scatter<<<(n_rope + 255) / 256, 256>>>(qkv, positions, q, k, v);

    // 3) flash attention (fp16 in, fp16 attn out)
    cudaFuncSetAttribute(flash_attn_h16, cudaFuncAttributeMaxDynamicSharedMemorySize,
                         FA_SMEM_BYTES);
    flash_attn_h16<<<dim3(S_ / 128, B_ * H_), 256, FA_SMEM_BYTES>>>(q, k, v, attn);

    // 4) dense projection (fp16 mma, fp32 output)
    h16_gemm_nt<<<dim3(HID_ / BN, T_ / BM), 256, GEMM_SMEM_BYTES>>>(
        attn, wd_h, out, T_, HID_, HID_);
}

// round 15
// speedup vs baseline: 2.7112x; 1.6783x over previous
#include <cuda_runtime.h>
#include <cuda_fp16.h>
#include <cstdint>
#include <stdint.h>
#include <math.h>

#define T_    4096
#define HID_  4096
#define B_    4
#define S_    1024
#define H_    32
#define HKV_  8
#define D_    128
#define NQKV_ 6144   // (H + 2*HKV) * D

// ---------------- scratch ---------------------------------------------------
__device__ float  g_qkv[(size_t)T_ * NQKV_];            // fp32 GEMM output
__device__ __half g_q[(size_t)B_ * H_ * S_ * D_];
__device__ __half g_k[(size_t)B_ * HKV_ * S_ * D_];
__device__ __half g_v[(size_t)B_ * HKV_ * S_ * D_];
__device__ __half g_attn[(size_t)T_ * HID_];
__device__ __half g_hid_h[(size_t)T_ * HID_];
__device__ __half g_wqkv_h[(size_t)NQKV_ * HID_];
__device__ __half g_wd_h[(size_t)HID_ * HID_];
__device__ float2 g_rtab[S_ * 64];                      // (cos, sin) per (pos, i)

// ---------------- helpers ---------------------------------------------------
__device__ __forceinline__ void cp16(unsigned int dst, const void* src) {
    asm volatile("cp.async.cg.shared.global [%0], [%1], 16;" :: "r"(dst), "l"(src));
}

__device__ __forceinline__ void mma_f16(float* c, const unsigned int* a,
                                        const unsigned int* b) {
    asm volatile(
        "mma.sync.aligned.m16n8k16.row.col.f32.f16.f16.f32 "
        "{%0,%1,%2,%3}, {%4,%5,%6,%7}, {%8,%9}, {%0,%1,%2,%3};\n"
        : "+f"(c[0]), "+f"(c[1]), "+f"(c[2]), "+f"(c[3])
        : "r"(a[0]), "r"(a[1]), "r"(a[2]), "r"(a[3]), "r"(b[0]), "r"(b[1]));
}

__device__ __forceinline__ void ldsm4(unsigned int* r, unsigned int addr) {
    asm volatile("ldmatrix.sync.aligned.m8n8.x4.shared.b16 {%0,%1,%2,%3}, [%4];"
        : "=r"(r[0]), "=r"(r[1]), "=r"(r[2]), "=r"(r[3]) : "r"(addr));
}

__device__ __forceinline__ void ldsm4t(unsigned int* r, unsigned int addr) {
    asm volatile("ldmatrix.sync.aligned.m8n8.x4.trans.shared.b16 {%0,%1,%2,%3}, [%4];"
        : "=r"(r[0]), "=r"(r[1]), "=r"(r[2]), "=r"(r[3]) : "r"(addr));
}

// ---------------- convert fp32 -> fp16 (RN) ---------------------------------
__global__ void to_half_kernel(const float* __restrict__ src,
                               __half* __restrict__ dst, int n4)
{
    int i = blockIdx.x * blockDim.x + threadIdx.x;
    if (i < n4) {
        float4 v = ((const float4*)src)[i];
        ((__half2*)dst)[2 * i]     = __floats2half2_rn(v.x, v.y);
        ((__half2*)dst)[2 * i + 1] = __floats2half2_rn(v.z, v.w);
    }
}

// ---------------- rope table (bitwise-identical math to inline version) -----
__global__ void build_rtab_kernel()
{
    int idx = blockIdx.x * 256 + threadIdx.x;   // 65536 threads
    int i   = idx & 63;
    int pos = idx >> 6;
    const double KF = 0.20762050593046014;      // log2(10000)/64
    double f = (double)pos * exp2(-(double)i * KF);
    double sv, cv; sincos(f, &sv, &cv);
    g_rtab[idx] = make_float2((float)cv, (float)sv);
}

// ---------------- fp16 GEMM: C = A[M,K] * W[N,K]^T, 3-stage, 1 barrier/iter -
#define BM 128
#define BN 128
#define LDT 36    // word pitch: 32 data words (64 halves) + 4 pad
#define NSTG 3
#define GEMM_STAGE_BYTES (BM * LDT * 4)                  // 18432 per matrix/stage
#define GEMM_SMEM_BYTES (NSTG * 2 * BM * LDT * 4)        // 110592

__global__ __launch_bounds__(256) void h16_gemm_nt(
    const __half* __restrict__ A, const __half* __restrict__ W,
    float* __restrict__ C, int M, int N, int K)
{
    extern __shared__ float sm[];
    float* As = sm;                           // [NSTG][128][36]
    float* Bs = sm + NSTG * BM * LDT;         // [NSTG][128][36]

    const int tid  = threadIdx.x;
    const int warp = tid >> 5, lane = tid & 31;
    const int wm   = (warp >> 2) * 64;
    const int wn   = (warp & 3) * 32;
    const int bm   = blockIdx.y * BM;
    const int bn   = blockIdx.x * BN;

    const unsigned int sA = (unsigned int)__cvta_generic_to_shared(As);
    const unsigned int sB = (unsigned int)__cvta_generic_to_shared(Bs);

    const int l7  = lane & 7;
    const int lg1 = (lane >> 3) & 1;
    const int lg2 = lane >> 4;
    const unsigned int aLane = (unsigned int)(((wm + l7 + 8 * lg1) * LDT + 4 * lg2) * 4);
    const unsigned int bLane = (unsigned int)(((wn + l7 + 8 * lg2) * LDT + 4 * lg1) * 4);

    const int lr  = tid >> 3;            // rows lr, +32, +64, +96
    const int lch = (tid & 7) * 8;       // half col
    const int lcw = (tid & 7) * 4;       // word col

    float acc[4][4][4];
    #pragma unroll
    for (int i = 0; i < 4; i++)
        #pragma unroll
        for (int j = 0; j < 4; j++)
            #pragma unroll
            for (int r = 0; r < 4; r++) acc[i][j][r] = 0.f;

    const int NT = K >> 6;   // BK = 64 halves

    // prologue: tiles 0,1 into stages 0,1 (one group each)
    #pragma unroll
    for (int p = 0; p < 2; p++) {
        const int k0 = p * 64;
        #pragma unroll
        for (int i = 0; i < 4; i++) {
            int r = lr + i * 32;
            cp16(sA + (unsigned int)((p * BM + r) * LDT + lcw) * 4,
                 A + (size_t)(bm + r) * K + k0 + lch);
            cp16(sB + (unsigned int)((p * BM + r) * LDT + lcw) * 4,
                 W + (size_t)(bn + r) * K + k0 + lch);
        }
        asm volatile("cp.async.commit_group;");
    }

    int cs = 0;   // compute stage (kt % 3)
    int ls = 2;   // load stage ((kt+2) % 3)

    for (int kt = 0; kt < NT; kt++) {
        // tile kt's group complete (only tile kt+1's group may be pending)
        asm volatile("cp.async.wait_group %0;" :: "n"(1));
        // all threads finished compute kt-1 -> stage ls reusable, stage cs visible
        __syncthreads();

        if (kt + 2 < NT) {
            const int k0 = (kt + 2) * 64;
            #pragma unroll
            for (int i = 0; i < 4; i++) {
                int r = lr + i * 32;
                cp16(sA + (unsigned int)((ls * BM + r) * LDT + lcw) * 4,
                     A + (size_t)(bm + r) * K + k0 + lch);
                cp16(sB + (unsigned int)((ls * BM + r) * LDT + lcw) * 4,
                     W + (size_t)(bn + r) * K + k0 + lch);
            }
        }
        asm volatile("cp.async.commit_group;");   // keeps group count aligned

        const unsigned int aBase = sA + (unsigned int)(cs * GEMM_STAGE_BYTES) + aLane;
        const unsigned int bBase = sB + (unsigned int)(cs * GEMM_STAGE_BYTES) + bLane;

        #pragma unroll
        for (int kk = 0; kk < 4; kk++) {
            unsigned int af[4][4], bf[2][4];
            #pragma unroll
            for (int mt = 0; mt < 4; mt++)
                ldsm4(af[mt], aBase + (unsigned int)(mt * 16 * LDT * 4 + kk * 32));
            #pragma unroll
            for (int j2 = 0; j2 < 2; j2++)
                ldsm4(bf[j2], bBase + (unsigned int)(j2 * 16 * LDT * 4 + kk * 32));
            #pragma unroll
            for (int mt = 0; mt < 4; mt++) {
                #pragma unroll
                for (int j2 = 0; j2 < 2; j2++) {
                    mma_f16(acc[mt][2 * j2],     af[mt], &bf[j2][0]);
                    mma_f16(acc[mt][2 * j2 + 1], af[mt], &bf[j2][2]);
                }
            }
        }
        // no second barrier: next iteration's barrier protects stage reuse

        cs = (cs + 1 == NSTG) ? 0 : cs + 1;
        ls = (ls + 1 == NSTG) ? 0 : ls + 1;
    }

    #pragma unroll
    for (int mt = 0; mt < 4; mt++) {
        #pragma unroll
        for (int nt = 0; nt < 4; nt++) {
            const int g  = lane >> 2, t4 = lane & 3;
            const int row0 = bm + wm + mt * 16 + g;
            const int col  = bn + wn + nt * 8 + 2 * t4;
            *(float2*)(C + (size_t)row0 * N + col)       = make_float2(acc[mt][nt][0], acc[mt][nt][1]);
            *(float2*)(C + (size_t)(row0 + 8) * N + col) = make_float2(acc[mt][nt][2], acc[mt][nt][3]);
        }
    }
}

// ---------------- RoPE + scatter (table-driven, fp16 out) -------------------
__global__ void rope_scatter(const float* __restrict__ qkv,
                             const int* __restrict__ positions,
                             __half* __restrict__ Qr, __half* __restrict__ Kr,
                             __half* __restrict__ Vr)
{
    const int NQ = T_ * H_ * 64;
    const int NK = T_ * HKV_ * 64;
    const int NV = T_ * HKV_ * 128;
    int idx = blockIdx.x * 256 + threadIdx.x;

    if (idx < NQ) {
        int i = idx & 63;
        int h = (idx >> 6) & 31;
        int t = idx >> 11;
        int pos = positions[t] & (S_ - 1);
        const float* row = qkv + (size_t)t * NQKV_ + h * 128;
        float x1 = row[i], x2 = row[64 + i];
        float2 cs_ = g_rtab[pos * 64 + i];
        int b = t >> 10, si = t & 1023;
        __half* out = Qr + (((size_t)(b * H_ + h)) * S_ + si) * 128;
        out[i]      = __float2half_rn(x1 * cs_.x - x2 * cs_.y);
        out[64 + i] = __float2half_rn(x2 * cs_.x + x1 * cs_.y);
    } else if (idx < NQ + NK) {
        int r = idx - NQ;
        int i = r & 63;
        int h = (r >> 6) & 7;
        int t = r >> 9;
        int pos = positions[t] & (S_ - 1);
        const float* row = qkv + (size_t)t * NQKV_ + H_ * 128 + h * 128;
        float x1 = row[i], x2 = row[64 + i];
        float2 cs_ = g_rtab[pos * 64 + i];
        int b = t >> 10, si = t & 1023;
        __half* out = Kr + (((size_t)(b * HKV_ + h)) * S_ + si) * 128;
        out[i]      = __float2half_rn(x1 * cs_.x - x2 * cs_.y);
        out[64 + i] = __float2half_rn(x2 * cs_.x + x1 * cs_.y);
    } else if (idx < NQ + NK + NV) {
        int r = idx - NQ - NK;
        int i = r & 127;
        int h = (r >> 7) & 7;
        int t = r >> 10;
        int b = t >> 10, si = t & 1023;
        Vr[(((size_t)(b * HKV_ + h)) * S_ + si) * 128 + i] =
            __float2half_rn(qkv[(size_t)t * NQKV_ + (H_ + HKV_) * 128 + h * 128 + i]);
    }
}

// ---------------- flash attention, fp16 mma (R13 known-good) ----------------
#define FA_LQ 68
#define FA_LP 36
#define FA_Q_WORDS (128 * FA_LQ)
#define FA_K_WORDS (64 * FA_LQ)
#define FA_V_WORDS (64 * FA_LQ)
#define FA_P_WORDS (128 * FA_LP)
#define FA_SMEM_BYTES ((FA_Q_WORDS + FA_K_WORDS + FA_V_WORDS + FA_P_WORDS) * 4)  // 88064

__global__ __launch_bounds__(256, 2) void flash_attn_h16(
    const __half* __restrict__ Q, const __half* __restrict__ Kg,
    const __half* __restrict__ Vg, __half* __restrict__ Out)
{
    extern __shared__ float sm[];
    float* Qs = sm;
    float* Ks = Qs + FA_Q_WORDS;
    float* Vs = Ks + FA_K_WORDS;
    float* Ps = Vs + FA_V_WORDS;

    const int qb = blockIdx.x;
    const int bh = blockIdx.y;
    const int b  = bh >> 5;
    const int h  = bh & 31;
    const int hkv = h >> 2;

    const __half* Qbase = Q  + ((size_t)bh * S_ + qb * 128) * D_;
    const __half* Kbase = Kg + ((size_t)(b * HKV_ + hkv) * S_) * D_;
    const __half* Vbase = Vg + ((size_t)(b * HKV_ + hkv) * S_) * D_;

    const int tid  = threadIdx.x;
    const int w    = tid >> 5, lane = tid & 31;
    const int g    = lane >> 2, t4 = lane & 3;
    const int wrow = w * 16;
    const float C = 0.12751743199276533f;   // (1/sqrt(128)) * log2(e)

    const unsigned int sQ = (unsigned int)__cvta_generic_to_shared(Qs);
    const unsigned int sK = (unsigned int)__cvta_generic_to_shared(Ks);
    const unsigned int sV = (unsigned int)__cvta_generic_to_shared(Vs);
    const unsigned int sP = (unsigned int)__cvta_generic_to_shared(Ps);

    const int l7  = lane & 7;
    const int lg1 = (lane >> 3) & 1;
    const int lg2 = lane >> 4;
    const unsigned int qLane = (unsigned int)(((wrow + l7 + 8 * lg1) * FA_LQ + 4 * lg2) * 4);
    const unsigned int kLane = (unsigned int)(((l7 + 8 * lg2) * FA_LQ + 4 * lg1) * 4);
    const unsigned int pLane = (unsigned int)(((wrow + l7 + 8 * lg1) * FA_LP + 4 * lg2) * 4);
    const unsigned int vLane = (unsigned int)((l7 + 8 * lg1) * FA_LQ * 4 + lg2 * 16);

    for (int i = tid; i < 128 * 16; i += 256) {
        int r = i >> 4, c = i & 15;
        cp16(sQ + (unsigned int)((r * FA_LQ + c * 4) * 4), Qbase + r * 128 + c * 8);
    }
    asm volatile("cp.async.commit_group;");

    float O[16][4];
    #pragma unroll
    for (int n = 0; n < 16; n++)
        #pragma unroll
        for (int r = 0; r < 4; r++) O[n][r] = 0.f;
    float m0 = -1e30f, m1 = -1e30f, l0 = 0.f, l1 = 0.f;

    const int jmax = 2 * qb + 1;
    for (int j = 0; j <= jmax; j++) {
        __syncthreads();
        for (int i = tid; i < 64 * 16; i += 256) {
            int r = i >> 4, c = i & 15;
            cp16(sK + (unsigned int)((r * FA_LQ + c * 4) * 4), Kbase + (j * 64 + r) * 128 + c * 8);
            cp16(sV + (unsigned int)((r * FA_LQ + c * 4) * 4), Vbase + (j * 64 + r) * 128 + c * 8);
        }
        asm volatile("cp.async.commit_group;");
        asm volatile("cp.async.wait_group 0;");
        __syncthreads();

        if (j * 64 > qb * 128 + wrow + 15) continue;

        float sfr[8][4];
        #pragma unroll
        for (int n = 0; n < 8; n++)
            #pragma unroll
            for (int r = 0; r < 4; r++) sfr[n][r] = 0.f;

        #pragma unroll
        for (int kk = 0; kk < 8; kk++) {
            unsigned int a[4];
            ldsm4(a, sQ + qLane + (unsigned int)(kk * 32));
            #pragma unroll
            for (int j2 = 0; j2 < 4; j2++) {
                unsigned int bfr[4];
                ldsm4(bfr, sK + kLane + (unsigned int)(j2 * 16 * FA_LQ * 4 + kk * 32));
                mma_f16(sfr[2 * j2],     a, &bfr[0]);
                mma_f16(sfr[2 * j2 + 1], a, &bfr[2]);
            }
        }

        const int qpos0 = qb * 128 + wrow + g;
        const int qpos1 = qpos0 + 8;
        if (j * 64 + 63 > qb * 128 + wrow) {
            #pragma unroll
            for (int nt = 0; nt < 8; nt++) {
                const int kc0 = j * 64 + nt * 8 + 2 * t4;
                if (kc0     > qpos0) sfr[nt][0] = -1e30f;
                if (kc0 + 1 > qpos0) sfr[nt][1] = -1e30f;
                if (kc0     > qpos1) sfr[nt][2] = -1e30f;
                if (kc0 + 1 > qpos1) sfr[nt][3] = -1e30f;
            }
        }

        float rm0 = -1e30f, rm1 = -1e30f;
        #pragma unroll
        for (int nt = 0; nt < 8; nt++) {
            rm0 = fmaxf(rm0, fmaxf(sfr[nt][0], sfr[nt][1]));
            rm1 = fmaxf(rm1, fmaxf(sfr[nt][2], sfr[nt][3]));
        }
        rm0 = fmaxf(rm0, __shfl_xor_sync(0xffffffffu, rm0, 1));
        rm0 = fmaxf(rm0, __shfl_xor_sync(0xffffffffu, rm0, 2));
        rm1 = fmaxf(rm1, __shfl_xor_sync(0xffffffffu, rm1, 1));
        rm1 = fmaxf(rm1, __shfl_xor_sync(0xffffffffu, rm1, 2));

        const float mn0 = fmaxf(m0, rm0);
        const float mn1 = fmaxf(m1, rm1);
        const float corr0 = exp2f((m0 - mn0) * C);
        const float corr1 = exp2f((m1 - mn1) * C);
        #pragma unroll
        for (int nt = 0; nt < 16; nt++) {
            O[nt][0] *= corr0; O[nt][1] *= corr0;
            O[nt][2] *= corr1; O[nt][3] *= corr1;
        }

        float ls0 = 0.f, ls1 = 0.f;
        #pragma unroll
        for (int nt = 0; nt < 8; nt++) {
            __half2 h0 = __floats2half2_rn(exp2f((sfr[nt][0] - mn0) * C),
                                           exp2f((sfr[nt][1] - mn0) * C));
            __half2 h1 = __floats2half2_rn(exp2f((sfr[nt][2] - mn1) * C),
                                           exp2f((sfr[nt][3] - mn1) * C));
            float2 f0 = __half22float2(h0);
            float2 f1 = __half22float2(h1);
            ls0 += f0.x + f0.y;
            ls1 += f1.x + f1.y;
            ((__half2*)Ps)[(wrow + g)     * FA_LP + nt * 4 + t4] = h0;
            ((__half2*)Ps)[(wrow + g + 8) * FA_LP + nt * 4 + t4] = h1;
        }
        ls0 += __shfl_xor_sync(0xffffffffu, ls0, 1);
        ls0 += __shfl_xor_sync(0xffffffffu, ls0, 2);
        ls1 += __shfl_xor_sync(0xffffffffu, ls1, 1);
        ls1 += __shfl_xor_sync(0xffffffffu, ls1, 2);
        l0 = l0 * corr0 + ls0;
        l1 = l1 * corr1 + ls1;
        m0 = mn0; m1 = mn1;

        __syncwarp();   // P rows are warp-private

        #pragma unroll
        for (int kk = 0; kk < 4; kk++) {
            unsigned int a[4];
            ldsm4(a, sP + pLane + (unsigned int)(kk * 32));
            #pragma unroll
            for (int jp = 0; jp < 8; jp++) {
                unsigned int bfr[4];
                ldsm4t(bfr, sV + vLane + (unsigned int)(kk * 16 * FA_LQ * 4 + jp * 32));
                mma_f16(O[2 * jp],     a, &bfr[0]);
                mma_f16(O[2 * jp + 1], a, &bfr[2]);
            }
        }
    }

    const float il0 = 1.f / l0;
    const float il1 = 1.f / l1;
    const int trow = b * S_ + qb * 128 + wrow + g;
    __half* o0 = Out + (size_t)trow * HID_ + h * 128;
    __half* o1 = o0 + (size_t)8 * HID_;
    #pragma unroll
    for (int nt = 0; nt < 16; nt++) {
        const int col = nt * 8 + 2 * t4;
        *(__half2*)(o0 + col) = __floats2half2_rn(O[nt][0] * il0, O[nt][1] * il0);
        *(__half2*)(o1 + col) = __floats2half2_rn(O[nt][2] * il1, O[nt][3] * il1);
    }
}

// ---------------- launch -----------------------------------------------------
extern "C" void kernel_launch(void* const* d_in, const int* in_sizes, int n_in,
                              void* d_out, int out_size)
{
    const int*   positions = (const int*)d_in[0];
    const float* hidden    = (const float*)d_in[1];
    const float* w_qkv     = (const float*)d_in[2];
    const float* w_dense   = (const float*)d_in[3];
    float*       out       = (float*)d_out;

    float *qkv;
    __half *q, *k, *v, *attn, *hid_h, *wqkv_h, *wd_h;
    cudaGetSymbolAddress((void**)&qkv,    g_qkv);
    cudaGetSymbolAddress((void**)&q,      g_q);
    cudaGetSymbolAddress((void**)&k,      g_k);
    cudaGetSymbolAddress((void**)&v,      g_v);
    cudaGetSymbolAddress((void**)&attn,   g_attn);
    cudaGetSymbolAddress((void**)&hid_h,  g_hid_h);
    cudaGetSymbolAddress((void**)&wqkv_h, g_wqkv_h);
    cudaGetSymbolAddress((void**)&wd_h,   g_wd_h);

    // 0) rope table + fp16 operand conversion
    build_rtab_kernel<<<256, 256>>>();
    {
        int n4;
        n4 = (T_ * HID_) / 4;
        to_half_kernel<<<(n4 + 255) / 256, 256>>>(hidden, hid_h, n4);
        n4 = (NQKV_ * HID_) / 4;
        to_half_kernel<<<(n4 + 255) / 256, 256>>>(w_qkv, wqkv_h, n4);
        n4 = (HID_ * HID_) / 4;
        to_half_kernel<<<(n4 + 255) / 256, 256>>>(w_dense, wd_h, n4);
    }

    // 1) QKV projection
    cudaFuncSetAttribute(h16_gemm_nt, cudaFuncAttributeMaxDynamicSharedMemorySize,
                         GEMM_SMEM_BYTES);
    h16_gemm_nt<<<dim3(NQKV_ / BN, T_ / BM), 256, GEMM_SMEM_BYTES>>>(
        hid_h, wqkv_h, qkv, T_, NQKV_, HID_);

    // 2) RoPE + scatter
    const int n_rope = T_ * H_ * 64 + T_ * HKV_ * 64 + T_ * HKV_ * 128;
    rope_scatter<<<(n_rope + 255) / 256, 256>>>(qkv, positions, q, k, v);

    // 3) flash attention (R13 known-good)
    cudaFuncSetAttribute(flash_attn_h16, cudaFuncAttributeMaxDynamicSharedMemorySize,
                         FA_SMEM_BYTES);
    flash_attn_h16<<<dim3(S_ / 128, B_ * H_), 256, FA_SMEM_BYTES>>>(q, k, v, attn);

    // 4) dense projection
    h16_gemm_nt<<<dim3(HID_ / BN, T_ / BM), 256, GEMM_SMEM_BYTES>>>(
        attn, wd_h, out, T_, HID_, HID_);
}

// round 17
// speedup vs baseline: 2.7365x; 1.0093x over previous
#include <cuda_runtime.h>
#include <cuda_fp16.h>
#include <cstdint>
#include <stdint.h>
#include <math.h>

#define T_    4096
#define HID_  4096
#define B_    4
#define S_    1024
#define H_    32
#define HKV_  8
#define D_    128
#define NQKV_ 6144   // (H + 2*HKV) * D

// ---------------- scratch ---------------------------------------------------
__device__ float  g_qkv[(size_t)T_ * NQKV_];            // fp32 GEMM output
__device__ __half g_q[(size_t)B_ * H_ * S_ * D_];
__device__ __half g_k[(size_t)B_ * HKV_ * S_ * D_];
__device__ __half g_v[(size_t)B_ * HKV_ * S_ * D_];
__device__ __half g_attn[(size_t)T_ * HID_];
__device__ __half g_hid_h[(size_t)T_ * HID_];
__device__ __half g_wqkv_h[(size_t)NQKV_ * HID_];
__device__ __half g_wd_h[(size_t)HID_ * HID_];
__device__ float2 g_rtab[S_ * 64];                      // (cos, sin) per (pos, i)

// ---------------- helpers ---------------------------------------------------
__device__ __forceinline__ void cp16(unsigned int dst, const void* src) {
    asm volatile("cp.async.cg.shared.global [%0], [%1], 16;" :: "r"(dst), "l"(src));
}

__device__ __forceinline__ void mma_f16(float* c, const unsigned int* a,
                                        const unsigned int* b) {
    asm volatile(
        "mma.sync.aligned.m16n8k16.row.col.f32.f16.f16.f32 "
        "{%0,%1,%2,%3}, {%4,%5,%6,%7}, {%8,%9}, {%0,%1,%2,%3};\n"
        : "+f"(c[0]), "+f"(c[1]), "+f"(c[2]), "+f"(c[3])
        : "r"(a[0]), "r"(a[1]), "r"(a[2]), "r"(a[3]), "r"(b[0]), "r"(b[1]));
}

__device__ __forceinline__ void ldsm4(unsigned int* r, unsigned int addr) {
    asm volatile("ldmatrix.sync.aligned.m8n8.x4.shared.b16 {%0,%1,%2,%3}, [%4];"
        : "=r"(r[0]), "=r"(r[1]), "=r"(r[2]), "=r"(r[3]) : "r"(addr));
}

__device__ __forceinline__ void ldsm4t(unsigned int* r, unsigned int addr) {
    asm volatile("ldmatrix.sync.aligned.m8n8.x4.trans.shared.b16 {%0,%1,%2,%3}, [%4];"
        : "=r"(r[0]), "=r"(r[1]), "=r"(r[2]), "=r"(r[3]) : "r"(addr));
}

__device__ __forceinline__ unsigned int h2u(__half2 h) {
    return *(unsigned int*)&h;
}

// ---------------- convert fp32 -> fp16 (RN) ---------------------------------
__global__ void to_half_kernel(const float* __restrict__ src,
                               __half* __restrict__ dst, int n4)
{
    int i = blockIdx.x * blockDim.x + threadIdx.x;
    if (i < n4) {
        float4 v = ((const float4*)src)[i];
        ((__half2*)dst)[2 * i]     = __floats2half2_rn(v.x, v.y);
        ((__half2*)dst)[2 * i + 1] = __floats2half2_rn(v.z, v.w);
    }
}

// ---------------- rope table (bitwise-identical math to inline version) -----
__global__ void build_rtab_kernel()
{
    int idx = blockIdx.x * 256 + threadIdx.x;   // 65536 threads
    int i   = idx & 63;
    int pos = idx >> 6;
    const double KF = 0.20762050593046014;      // log2(10000)/64
    double f = (double)pos * exp2(-(double)i * KF);
    double sv, cv; sincos(f, &sv, &cv);
    g_rtab[idx] = make_float2((float)cv, (float)sv);
}

// ---------------- fp16 GEMM: C = A[M,K] * W[N,K]^T, 3-stage, 1 barrier/iter -
#define BM 128
#define BN 128
#define LDT 36    // word pitch: 32 data words (64 halves) + 4 pad
#define NSTG 3
#define GEMM_STAGE_BYTES (BM * LDT * 4)                  // 18432 per matrix/stage
#define GEMM_SMEM_BYTES (NSTG * 2 * BM * LDT * 4)        // 110592

__global__ __launch_bounds__(256) void h16_gemm_nt(
    const __half* __restrict__ A, const __half* __restrict__ W,
    float* __restrict__ C, int M, int N, int K)
{
    extern __shared__ float sm[];
    float* As = sm;                           // [NSTG][128][36]
    float* Bs = sm + NSTG * BM * LDT;         // [NSTG][128][36]

    const int tid  = threadIdx.x;
    const int warp = tid >> 5, lane = tid & 31;
    const int wm   = (warp >> 2) * 64;
    const int wn   = (warp & 3) * 32;
    const int bm   = blockIdx.y * BM;
    const int bn   = blockIdx.x * BN;

    const unsigned int sA = (unsigned int)__cvta_generic_to_shared(As);
    const unsigned int sB = (unsigned int)__cvta_generic_to_shared(Bs);

    const int l7  = lane & 7;
    const int lg1 = (lane >> 3) & 1;
    const int lg2 = lane >> 4;
    const unsigned int aLane = (unsigned int)(((wm + l7 + 8 * lg1) * LDT + 4 * lg2) * 4);
    const unsigned int bLane = (unsigned int)(((wn + l7 + 8 * lg2) * LDT + 4 * lg1) * 4);

    const int lr  = tid >> 3;            // rows lr, +32, +64, +96
    const int lch = (tid & 7) * 8;       // half col
    const int lcw = (tid & 7) * 4;       // word col

    float acc[4][4][4];
    #pragma unroll
    for (int i = 0; i < 4; i++)
        #pragma unroll
        for (int j = 0; j < 4; j++)
            #pragma unroll
            for (int r = 0; r < 4; r++) acc[i][j][r] = 0.f;

    const int NT = K >> 6;   // BK = 64 halves

    // prologue: tiles 0,1 into stages 0,1 (one group each)
    #pragma unroll
    for (int p = 0; p < 2; p++) {
        const int k0 = p * 64;
        #pragma unroll
        for (int i = 0; i < 4; i++) {
            int r = lr + i * 32;
            cp16(sA + (unsigned int)((p * BM + r) * LDT + lcw) * 4,
                 A + (size_t)(bm + r) * K + k0 + lch);
            cp16(sB + (unsigned int)((p * BM + r) * LDT + lcw) * 4,
                 W + (size_t)(bn + r) * K + k0 + lch);
        }
        asm volatile("cp.async.commit_group;");
    }

    int cs = 0;   // compute stage (kt % 3)
    int ls = 2;   // load stage ((kt+2) % 3)

    for (int kt = 0; kt < NT; kt++) {
        asm volatile("cp.async.wait_group %0;" :: "n"(1));
        __syncthreads();

        if (kt + 2 < NT) {
            const int k0 = (kt + 2) * 64;
            #pragma unroll
            for (int i = 0; i < 4; i++) {
                int r = lr + i * 32;
                cp16(sA + (unsigned int)((ls * BM + r) * LDT + lcw) * 4,
                     A + (size_t)(bm + r) * K + k0 + lch);
                cp16(sB + (unsigned int)((ls * BM + r) * LDT + lcw) * 4,
                     W + (size_t)(bn + r) * K + k0 + lch);
            }
        }
        asm volatile("cp.async.commit_group;");   // keeps group count aligned

        const unsigned int aBase = sA + (unsigned int)(cs * GEMM_STAGE_BYTES) + aLane;
        const unsigned int bBase = sB + (unsigned int)(cs * GEMM_STAGE_BYTES) + bLane;

        #pragma unroll
        for (int kk = 0; kk < 4; kk++) {
            unsigned int af[4][4], bf[2][4];
            #pragma unroll
            for (int mt = 0; mt < 4; mt++)
                ldsm4(af[mt], aBase + (unsigned int)(mt * 16 * LDT * 4 + kk * 32));
            #pragma unroll
            for (int j2 = 0; j2 < 2; j2++)
                ldsm4(bf[j2], bBase + (unsigned int)(j2 * 16 * LDT * 4 + kk * 32));
            #pragma unroll
            for (int mt = 0; mt < 4; mt++) {
                #pragma unroll
                for (int j2 = 0; j2 < 2; j2++) {
                    mma_f16(acc[mt][2 * j2],     af[mt], &bf[j2][0]);
                    mma_f16(acc[mt][2 * j2 + 1], af[mt], &bf[j2][2]);
                }
            }
        }

        cs = (cs + 1 == NSTG) ? 0 : cs + 1;
        ls = (ls + 1 == NSTG) ? 0 : ls + 1;
    }

    #pragma unroll
    for (int mt = 0; mt < 4; mt++) {
        #pragma unroll
        for (int nt = 0; nt < 4; nt++) {
            const int g  = lane >> 2, t4 = lane & 3;
            const int row0 = bm + wm + mt * 16 + g;
            const int col  = bn + wn + nt * 8 + 2 * t4;
            *(float2*)(C + (size_t)row0 * N + col)       = make_float2(acc[mt][nt][0], acc[mt][nt][1]);
            *(float2*)(C + (size_t)(row0 + 8) * N + col) = make_float2(acc[mt][nt][2], acc[mt][nt][3]);
        }
    }
}

// ---------------- RoPE + scatter (table-driven, fp16 out) -------------------
__global__ void rope_scatter(const float* __restrict__ qkv,
                             const int* __restrict__ positions,
                             __half* __restrict__ Qr, __half* __restrict__ Kr,
                             __half* __restrict__ Vr)
{
    const int NQ = T_ * H_ * 64;
    const int NK = T_ * HKV_ * 64;
    const int NV = T_ * HKV_ * 128;
    int idx = blockIdx.x * 256 + threadIdx.x;

    if (idx < NQ) {
        int i = idx & 63;
        int h = (idx >> 6) & 31;
        int t = idx >> 11;
        int pos = positions[t] & (S_ - 1);
        const float* row = qkv + (size_t)t * NQKV_ + h * 128;
        float x1 = row[i], x2 = row[64 + i];
        float2 cs_ = g_rtab[pos * 64 + i];
        int b = t >> 10, si = t & 1023;
        __half* out = Qr + (((size_t)(b * H_ + h)) * S_ + si) * 128;
        out[i]      = __float2half_rn(x1 * cs_.x - x2 * cs_.y);
        out[64 + i] = __float2half_rn(x2 * cs_.x + x1 * cs_.y);
    } else if (idx < NQ + NK) {
        int r = idx - NQ;
        int i = r & 63;
        int h = (r >> 6) & 7;
        int t = r >> 9;
        int pos = positions[t] & (S_ - 1);
        const float* row = qkv + (size_t)t * NQKV_ + H_ * 128 + h * 128;
        float x1 = row[i], x2 = row[64 + i];
        float2 cs_ = g_rtab[pos * 64 + i];
        int b = t >> 10, si = t & 1023;
        __half* out = Kr + (((size_t)(b * HKV_ + h)) * S_ + si) * 128;
        out[i]      = __float2half_rn(x1 * cs_.x - x2 * cs_.y);
        out[64 + i] = __float2half_rn(x2 * cs_.x + x1 * cs_.y);
    } else if (idx < NQ + NK + NV) {
        int r = idx - NQ - NK;
        int i = r & 127;
        int h = (r >> 7) & 7;
        int t = r >> 10;
        int b = t >> 10, si = t & 1023;
        Vr[(((size_t)(b * HKV_ + h)) * S_ + si) * 128 + i] =
            __float2half_rn(qkv[(size_t)t * NQKV_ + (H_ + HKV_) * 128 + h * 128 + i]);
    }
}

// ---------------- flash attention, fp16 mma ---------------------------------
// Register-resident P (FA2 layout identity) + KV double-buffer, 2 barriers/iter.
#define FA_LQ 68
#define FA_Q_WORDS  (128 * FA_LQ)             // 8704 words = 34816 B
#define FA_KV_STAGE_WORDS (2 * 64 * FA_LQ)    // K + V, 8704 words = 34816 B
#define FA_V_OFF_BYTES (64 * FA_LQ * 4)       // V offset within a stage
#define FA_SMEM_BYTES ((FA_Q_WORDS + 2 * FA_KV_STAGE_WORDS) * 4)   // 104448

__global__ __launch_bounds__(256, 2) void flash_attn_h16(
    const __half* __restrict__ Q, const __half* __restrict__ Kg,
    const __half* __restrict__ Vg, __half* __restrict__ Out)
{
    extern __shared__ float sm[];
    float* Qs = sm;

    const int qb = blockIdx.x;
    const int bh = blockIdx.y;
    const int b  = bh >> 5;
    const int h  = bh & 31;
    const int hkv = h >> 2;

    const __half* Qbase = Q  + ((size_t)bh * S_ + qb * 128) * D_;
    const __half* Kbase = Kg + ((size_t)(b * HKV_ + hkv) * S_) * D_;
    const __half* Vbase = Vg + ((size_t)(b * HKV_ + hkv) * S_) * D_;

    const int tid  = threadIdx.x;
    const int w    = tid >> 5, lane = tid & 31;
    const int g    = lane >> 2, t4 = lane & 3;
    const int wrow = w * 16;
    const float C = 0.12751743199276533f;   // (1/sqrt(128)) * log2(e)

    const unsigned int sQ  = (unsigned int)__cvta_generic_to_shared(Qs);
    const unsigned int sKV = sQ + FA_Q_WORDS * 4;

    const int l7  = lane & 7;
    const int lg1 = (lane >> 3) & 1;
    const int lg2 = lane >> 4;
    const unsigned int qLane = (unsigned int)(((wrow + l7 + 8 * lg1) * FA_LQ + 4 * lg2) * 4);
    const unsigned int kLane = (unsigned int)(((l7 + 8 * lg2) * FA_LQ + 4 * lg1) * 4);
    const unsigned int vLane = (unsigned int)((l7 + 8 * lg1) * FA_LQ * 4 + lg2 * 16);

    // prologue: Q group, then KV(0) group
    for (int i = tid; i < 128 * 16; i += 256) {
        int r = i >> 4, c = i & 15;
        cp16(sQ + (unsigned int)((r * FA_LQ + c * 4) * 4), Qbase + r * 128 + c * 8);
    }
    asm volatile("cp.async.commit_group;");
    for (int i = tid; i < 64 * 16; i += 256) {
        int r = i >> 4, c = i & 15;
        cp16(sKV + (unsigned int)((r * FA_LQ + c * 4) * 4), Kbase + r * 128 + c * 8);
        cp16(sKV + FA_V_OFF_BYTES + (unsigned int)((r * FA_LQ + c * 4) * 4),
             Vbase + r * 128 + c * 8);
    }
    asm volatile("cp.async.commit_group;");

    float O[16][4];
    #pragma unroll
    for (int n = 0; n < 16; n++)
        #pragma unroll
        for (int r = 0; r < 4; r++) O[n][r] = 0.f;
    float m0 = -1e30f, m1 = -1e30f, l0 = 0.f, l1 = 0.f;

    const int jmax = 2 * qb + 1;
    for (int j = 0; j <= jmax; j++) {
        // B1: all threads done computing on stage (j-1)&1 -> its reuse is safe
        __syncthreads();

        if (j + 1 <= jmax) {
            const unsigned int dst = sKV +
                (unsigned int)(((j + 1) & 1) * FA_KV_STAGE_WORDS * 4);
            for (int i = tid; i < 64 * 16; i += 256) {
                int r = i >> 4, c = i & 15;
                cp16(dst + (unsigned int)((r * FA_LQ + c * 4) * 4),
                     Kbase + ((j + 1) * 64 + r) * 128 + c * 8);
                cp16(dst + FA_V_OFF_BYTES + (unsigned int)((r * FA_LQ + c * 4) * 4),
                     Vbase + ((j + 1) * 64 + r) * 128 + c * 8);
            }
        }
        asm volatile("cp.async.commit_group;");   // always: group count aligned

        // KV(j) group complete (only KV(j+1) group may be pending); Q done too
        asm volatile("cp.async.wait_group %0;" :: "n"(1));
        __syncthreads();   // B2: visibility

        const bool active = (j * 64 <= qb * 128 + wrow + 15);
        if (active) {
            const unsigned int stg = sKV +
                (unsigned int)((j & 1) * FA_KV_STAGE_WORDS * 4);

            // ---- S = Q Kt ----
            float sfr[8][4];
            #pragma unroll
            for (int n = 0; n < 8; n++)
                #pragma unroll
                for (int r = 0; r < 4; r++) sfr[n][r] = 0.f;

            #pragma unroll
            for (int kk = 0; kk < 8; kk++) {
                unsigned int a[4];
                ldsm4(a, sQ + qLane + (unsigned int)(kk * 32));
                #pragma unroll
                for (int j2 = 0; j2 < 4; j2++) {
                    unsigned int bfr[4];
                    ldsm4(bfr, stg + kLane + (unsigned int)(j2 * 16 * FA_LQ * 4 + kk * 32));
                    mma_f16(sfr[2 * j2],     a, &bfr[0]);
                    mma_f16(sfr[2 * j2 + 1], a, &bfr[2]);
                }
            }

            // ---- causal mask ----
            const int qpos0 = qb * 128 + wrow + g;
            const int qpos1 = qpos0 + 8;
            if (j * 64 + 63 > qb * 128 + wrow) {
                #pragma unroll
                for (int nt = 0; nt < 8; nt++) {
                    const int kc0 = j * 64 + nt * 8 + 2 * t4;
                    if (kc0     > qpos0) sfr[nt][0] = -1e30f;
                    if (kc0 + 1 > qpos0) sfr[nt][1] = -1e30f;
                    if (kc0     > qpos1) sfr[nt][2] = -1e30f;
                    if (kc0 + 1 > qpos1) sfr[nt][3] = -1e30f;
                }
            }

            // ---- online softmax ----
            float rm0 = -1e30f, rm1 = -1e30f;
            #pragma unroll
            for (int nt = 0; nt < 8; nt++) {
                rm0 = fmaxf(rm0, fmaxf(sfr[nt][0], sfr[nt][1]));
                rm1 = fmaxf(rm1, fmaxf(sfr[nt][2], sfr[nt][3]));
            }
            rm0 = fmaxf(rm0, __shfl_xor_sync(0xffffffffu, rm0, 1));
            rm0 = fmaxf(rm0, __shfl_xor_sync(0xffffffffu, rm0, 2));
            rm1 = fmaxf(rm1, __shfl_xor_sync(0xffffffffu, rm1, 1));
            rm1 = fmaxf(rm1, __shfl_xor_sync(0xffffffffu, rm1, 2));

            const float mn0 = fmaxf(m0, rm0);
            const float mn1 = fmaxf(m1, rm1);
            const float corr0 = exp2f((m0 - mn0) * C);
            const float corr1 = exp2f((m1 - mn1) * C);
            #pragma unroll
            for (int nt = 0; nt < 16; nt++) {
                O[nt][0] *= corr0; O[nt][1] *= corr0;
                O[nt][2] *= corr1; O[nt][3] *= corr1;
            }

            // ---- P in registers: accumulator frag == A frag (m16n8k16) ----
            unsigned int pfr[8][2];
            float ls0 = 0.f, ls1 = 0.f;
            #pragma unroll
            for (int nt = 0; nt < 8; nt++) {
                __half2 h0 = __floats2half2_rn(exp2f((sfr[nt][0] - mn0) * C),
                                               exp2f((sfr[nt][1] - mn0) * C));
                __half2 h1 = __floats2half2_rn(exp2f((sfr[nt][2] - mn1) * C),
                                               exp2f((sfr[nt][3] - mn1) * C));
                float2 f0 = __half22float2(h0);
                float2 f1 = __half22float2(h1);
                ls0 += f0.x + f0.y;
                ls1 += f1.x + f1.y;
                pfr[nt][0] = h2u(h0);
                pfr[nt][1] = h2u(h1);
            }
            ls0 += __shfl_xor_sync(0xffffffffu, ls0, 1);
            ls0 += __shfl_xor_sync(0xffffffffu, ls0, 2);
            ls1 += __shfl_xor_sync(0xffffffffu, ls1, 1);
            ls1 += __shfl_xor_sync(0xffffffffu, ls1, 2);
            l0 = l0 * corr0 + ls0;
            l1 = l1 * corr1 + ls1;
            m0 = mn0; m1 = mn1;

            // ---- O += P V ----
            #pragma unroll
            for (int kk = 0; kk < 4; kk++) {
                unsigned int a[4];
                a[0] = pfr[2 * kk][0];
                a[1] = pfr[2 * kk][1];
                a[2] = pfr[2 * kk + 1][0];
                a[3] = pfr[2 * kk + 1][1];
                #pragma unroll
                for (int jp = 0; jp < 8; jp++) {
                    unsigned int bfr[4];
                    ldsm4t(bfr, stg + FA_V_OFF_BYTES + vLane +
                                (unsigned int)(kk * 16 * FA_LQ * 4 + jp * 32));
                    mma_f16(O[2 * jp],     a, &bfr[0]);
                    mma_f16(O[2 * jp + 1], a, &bfr[2]);
                }
            }
        }
    }

    // epilogue
    const float il0 = 1.f / l0;
    const float il1 = 1.f / l1;
    const int trow = b * S_ + qb * 128 + wrow + g;
    __half* o0 = Out + (size_t)trow * HID_ + h * 128;
    __half* o1 = o0 + (size_t)8 * HID_;
    #pragma unroll
    for (int nt = 0; nt < 16; nt++) {
        const int col = nt * 8 + 2 * t4;
        *(__half2*)(o0 + col) = __floats2half2_rn(O[nt][0] * il0, O[nt][1] * il0);
        *(__half2*)(o1 + col) = __floats2half2_rn(O[nt][2] * il1, O[nt][3] * il1);
    }
}

// ---------------- launch -----------------------------------------------------
extern "C" void kernel_launch(void* const* d_in, const int* in_sizes, int n_in,
                              void* d_out, int out_size)
{
    const int*   positions = (const int*)d_in[0];
    const float* hidden    = (const float*)d_in[1];
    const float* w_qkv     = (const float*)d_in[2];
    const float* w_dense   = (const float*)d_in[3];
    float*       out       = (float*)d_out;

    float *qkv;
    __half *q, *k, *v, *attn, *hid_h, *wqkv_h, *wd_h;
    cudaGetSymbolAddress((void**)&qkv,    g_qkv);
    cudaGetSymbolAddress((void**)&q,      g_q);
    cudaGetSymbolAddress((void**)&k,      g_k);
    cudaGetSymbolAddress((void**)&v,      g_v);
    cudaGetSymbolAddress((void**)&attn,   g_attn);
    cudaGetSymbolAddress((void**)&hid_h,  g_hid_h);
    cudaGetSymbolAddress((void**)&wqkv_h, g_wqkv_h);
    cudaGetSymbolAddress((void**)&wd_h,   g_wd_h);

    // 0) rope table + fp16 operand conversion
    build_rtab_kernel<<<256, 256>>>();
    {
        int n4;
        n4 = (T_ * HID_) / 4;
        to_half_kernel<<<(n4 + 255) / 256, 256>>>(hidden, hid_h, n4);
        n4 = (NQKV_ * HID_) / 4;
        to_half_kernel<<<(n4 + 255) / 256, 256>>>(w_qkv, wqkv_h, n4);
        n4 = (HID_ * HID_) / 4;
        to_half_kernel<<<(n4 + 255) / 256, 256>>>(w_dense, wd_h, n4);
    }

    // 1) QKV projection
    cudaFuncSetAttribute(h16_gemm_nt, cudaFuncAttributeMaxDynamicSharedMemorySize,
                         GEMM_SMEM_BYTES);
    h16_gemm_nt<<<dim3(NQKV_ / BN, T_ / BM), 256, GEMM_SMEM_BYTES>>>(
        hid_h, wqkv_h, qkv, T_, NQKV_, HID_);

    // 2) RoPE + scatter
    const int n_rope = T_ * H_ * 64 + T_ * HKV_ * 64 + T_ * HKV_ * 128;
    rope_scatter<<<(n_rope + 255) / 256, 256>>>(qkv, positions, q, k, v);

    // 3) flash attention
    cudaFuncSetAttribute(flash_attn_h16, cudaFuncAttributeMaxDynamicSharedMemorySize,
                         FA_SMEM_BYTES);
    flash_attn_h16<<<dim3(S_ / 128, B_ * H_), 256, FA_SMEM_BYTES>>>(q, k, v, attn);

    // 4) dense projection
    h16_gemm_nt<<<dim3(HID_ / BN, T_ / BM), 256, GEMM_SMEM_BYTES>>>(
        attn, wd_h, out, T_, HID_, HID_);
}